// round 1
// baseline (speedup 1.0000x reference)
#include <cuda_runtime.h>
#include <cstdint>

// Problem shape constants (fixed by the dataset; runtime dims read from in_sizes
// where cheap, but scratch is statically sized).
#define DF 128          // feature dim
#define DH 512          // hidden dim
#define MAXN 10000      // nodes
#define MAXG 128        // >= n_graphs (100)

// -------- static device scratch (no allocations allowed) --------
__device__ float g_tmp[MAXN * DH];    // relu(nodes@W1+b1)   ~20.5 MB
__device__ float g_h[MAXN * DF];      // final node features  ~5.1 MB (L2-resident)
__device__ float g_wsum[MAXG];        // per-graph sum of edge weights
__device__ float g_esum[MAXG];        // per-graph sum of w * dist^2
__device__ int   g_eoff[MAXG + 1];    // edge prefix offsets
__device__ int   g_nid[MAXG];         // node ids = cumsum(n_node)-1

// ============================================================================
// Kernel 0: prefix sums + zero accumulators (must run every replay!)
// ============================================================================
__global__ void prefix_kernel(const int* __restrict__ n_node,
                              const int* __restrict__ n_edge, int G) {
    int t = threadIdx.x;
    if (t < MAXG) { g_wsum[t] = 0.f; g_esum[t] = 0.f; }
    if (t == 0) {
        int ea = 0, na = 0;
        g_eoff[0] = 0;
        for (int g = 0; g < G; g++) {
            ea += n_edge[g]; g_eoff[g + 1] = ea;
            na += n_node[g]; g_nid[g] = na - 1;
        }
    }
}

// ============================================================================
// Tiled SGEMM: C[M,N] = act(A[M,K] @ B[K,N] + bias)
// 64x64 block tile, BK=32, 256 threads, 4x4 micro-tile per thread.
// N, K assumed divisible by 64/32 (true: 512,128); M bounds-guarded.
// ============================================================================
__global__ __launch_bounds__(256)
void gemm_bias_act(const float* __restrict__ A, const float* __restrict__ B,
                   const float* __restrict__ bias, float* __restrict__ C,
                   int M, int N, int K, int doRelu) {
    const int BM = 64, BN = 64, BK = 32;
    __shared__ float As[BM][BK + 4];   // +4 keeps float4 STS aligned, breaks conflicts
    __shared__ float Bs[BK][BN + 4];

    int tid = threadIdx.x;
    int tx = tid & 15;        // 0..15 -> 4 cols each
    int ty = tid >> 4;        // 0..15 -> 4 rows each
    int row0 = blockIdx.y * BM;
    int col0 = blockIdx.x * BN;

    float acc[4][4] = {};

    for (int k0 = 0; k0 < K; k0 += BK) {
        // --- load A tile (64x32) : 512 float4, 2 per thread ---
        #pragma unroll
        for (int i = 0; i < 2; i++) {
            int lin = tid + i * 256;
            int r = lin >> 3;              // row within tile
            int c4 = (lin & 7) * 4;        // k within tile
            int row = row0 + r;
            float4 v = make_float4(0.f, 0.f, 0.f, 0.f);
            if (row < M)
                v = *(const float4*)(A + (size_t)row * K + k0 + c4);
            *(float4*)&As[r][c4] = v;
        }
        // --- load B tile (32x64) ---
        #pragma unroll
        for (int i = 0; i < 2; i++) {
            int lin = tid + i * 256;
            int kk = lin >> 4;
            int c4 = (lin & 15) * 4;
            float4 v = *(const float4*)(B + (size_t)(k0 + kk) * N + col0 + c4);
            *(float4*)&Bs[kk][c4] = v;
        }
        __syncthreads();

        #pragma unroll
        for (int k = 0; k < BK; k++) {
            float4 b4 = *(const float4*)&Bs[k][tx * 4];
            #pragma unroll
            for (int i = 0; i < 4; i++) {
                float a = As[ty * 4 + i][k];
                acc[i][0] += a * b4.x;
                acc[i][1] += a * b4.y;
                acc[i][2] += a * b4.z;
                acc[i][3] += a * b4.w;
            }
        }
        __syncthreads();
    }

    // epilogue: bias + optional relu
    #pragma unroll
    for (int i = 0; i < 4; i++) {
        int row = row0 + ty * 4 + i;
        if (row >= M) continue;
        #pragma unroll
        for (int j = 0; j < 4; j++) {
            int col = col0 + tx * 4 + j;
            float v = acc[i][j] + bias[col];
            if (doRelu) v = fmaxf(v, 0.f);
            C[(size_t)row * N + col] = v;
        }
    }
}

// ============================================================================
// Edge kernel: one warp per edge. Lane l handles float4 chunk l of the
// 128-float rows h[sender], h[receiver]; warp-reduce squared distance;
// per-block merge of (graph_id, val, w) runs before atomics.
// ============================================================================
__global__ __launch_bounds__(256)
void edge_kernel(const float* __restrict__ ew,
                 const int* __restrict__ snd, const int* __restrict__ rcv,
                 int E, int G) {
    __shared__ int   s_gid[8];
    __shared__ float s_val[8];
    __shared__ float s_w[8];

    int lane = threadIdx.x & 31;
    int wl = threadIdx.x >> 5;
    int e = (blockIdx.x * blockDim.x + threadIdx.x) >> 5;

    int gid = -1; float val = 0.f, w = 0.f;
    if (e < E) {
        int s = snd[e];
        int r = rcv[e];
        const float4* hs = (const float4*)(g_h + (size_t)s * DF);
        const float4* hr = (const float4*)(g_h + (size_t)r * DF);
        float4 a = hs[lane];
        float4 b = hr[lane];
        float d0 = a.x - b.x, d1 = a.y - b.y, d2 = a.z - b.z, d3 = a.w - b.w;
        float sum = d0 * d0 + d1 * d1 + d2 * d2 + d3 * d3;
        #pragma unroll
        for (int off = 16; off; off >>= 1)
            sum += __shfl_xor_sync(0xffffffffu, sum, off);
        if (lane == 0) {
            float we = ew[e];
            w = we;
            val = we * sum;
            // last g with eoff[g] <= e
            int lo = 0, hi = G;
            while (hi - lo > 1) {
                int mid = (lo + hi) >> 1;
                if (g_eoff[mid] <= e) lo = mid; else hi = mid;
            }
            gid = lo;
        }
    }
    if (lane == 0) { s_gid[wl] = gid; s_val[wl] = val; s_w[wl] = w; }
    __syncthreads();
    if (threadIdx.x == 0) {
        int cg = -1; float av = 0.f, aw = 0.f;
        #pragma unroll
        for (int i = 0; i < 8; i++) {
            int gi = s_gid[i];
            if (gi < 0) continue;
            if (gi != cg) {
                if (cg >= 0) { atomicAdd(&g_esum[cg], av); atomicAdd(&g_wsum[cg], aw); }
                cg = gi; av = 0.f; aw = 0.f;
            }
            av += s_val[i]; aw += s_w[i];
        }
        if (cg >= 0) { atomicAdd(&g_esum[cg], av); atomicAdd(&g_wsum[cg], aw); }
    }
}

// ============================================================================
// Output kernel: gather node_out rows; block 0 also computes the mean loss.
// ============================================================================
__global__ void out_kernel(float* __restrict__ out, int G, int lossIdx) {
    int g = blockIdx.x;
    int t = threadIdx.x;
    if (g < G)
        out[g * DF + t] = g_h[(size_t)g_nid[g] * DF + t];
    if (g == 0) {
        __shared__ float red[128];
        float term = 0.f;
        if (t < G) {
            float w = g_wsum[t];
            term = (w != 0.f) ? (g_esum[t] / w) : 0.f;
        }
        red[t] = term;
        __syncthreads();
        #pragma unroll
        for (int s = 64; s; s >>= 1) {
            if (t < s) red[t] += red[t + s];
            __syncthreads();
        }
        if (t == 0) out[lossIdx] = red[0] / (float)G;
    }
}

// ============================================================================
extern "C" void kernel_launch(void* const* d_in, const int* in_sizes, int n_in,
                              void* d_out, int out_size) {
    const float* nodes     = (const float*)d_in[0];
    // d_in[1] = edges (E,1)
    const float* edges     = (const float*)d_in[1];
    const int*   senders   = (const int*)d_in[2];
    const int*   receivers = (const int*)d_in[3];
    const int*   n_node    = (const int*)d_in[4];
    const int*   n_edge    = (const int*)d_in[5];
    const float* W1        = (const float*)d_in[6];
    const float* b1        = (const float*)d_in[7];
    const float* W2        = (const float*)d_in[8];
    const float* b2        = (const float*)d_in[9];
    float* out = (float*)d_out;

    int M = in_sizes[0] / DF;   // 10000 nodes
    int E = in_sizes[2];        // 640000 edges
    int G = in_sizes[4];        // 100 graphs

    void *p_tmp = nullptr, *p_h = nullptr;
    cudaGetSymbolAddress(&p_tmp, g_tmp);
    cudaGetSymbolAddress(&p_h, g_h);

    prefix_kernel<<<1, 128>>>(n_node, n_edge, G);

    dim3 g1(DH / 64, (M + 63) / 64);
    gemm_bias_act<<<g1, 256>>>(nodes, W1, b1, (float*)p_tmp, M, DH, DF, 1);

    dim3 g2(DF / 64, (M + 63) / 64);
    gemm_bias_act<<<g2, 256>>>((float*)p_tmp, W2, b2, (float*)p_h, M, DF, DH, 0);

    int eblocks = (E + 7) / 8;   // 8 warps (edges) per 256-thread block
    edge_kernel<<<eblocks, 256>>>(edges, senders, receivers, E, G);

    out_kernel<<<G, 128>>>(out, G, out_size - 1);
}

// round 3
// speedup vs baseline: 1.7852x; 1.7852x over previous
#include <cuda_runtime.h>
#include <cstdint>

#define DF 128          // feature dim
#define DH 512          // hidden dim
#define MAXN 10000      // nodes
#define MAXG 128        // >= n_graphs (100)
#define EPW 32          // edges per warp strip

// -------- static device scratch (no allocations allowed) --------
__device__ float g_tmp[MAXN * DH];    // relu(nodes@W1+b1)
__device__ float g_h[MAXN * DF];      // final node features (L2-resident, 5.1MB)
__device__ float g_wsum[MAXG];
__device__ float g_esum[MAXG];
__device__ int   g_eoff[MAXG + 1];
__device__ int   g_nid[MAXG];

// ============================================================================
// Kernel 0: prefix sums + zero accumulators (runs every replay)
// ============================================================================
__global__ void prefix_kernel(const int* __restrict__ n_node,
                              const int* __restrict__ n_edge, int G) {
    int t = threadIdx.x;
    if (t < MAXG) { g_wsum[t] = 0.f; g_esum[t] = 0.f; }
    if (t == 0) {
        int ea = 0, na = 0;
        g_eoff[0] = 0;
        for (int g = 0; g < G; g++) {
            ea += n_edge[g]; g_eoff[g + 1] = ea;
            na += n_node[g]; g_nid[g] = na - 1;
        }
    }
}

// ============================================================================
// Tiled SGEMM: C[M,N] = act(A[M,K] @ B[K,N] + bias)
// 64x64 tile, BK=32, 256 threads, 4x4 micro-tile.
// ============================================================================
__global__ __launch_bounds__(256)
void gemm_bias_act(const float* __restrict__ A, const float* __restrict__ B,
                   const float* __restrict__ bias, float* __restrict__ C,
                   int M, int N, int K, int doRelu) {
    const int BM = 64, BN = 64, BK = 32;
    __shared__ float As[BM][BK + 4];
    __shared__ float Bs[BK][BN + 4];

    int tid = threadIdx.x;
    int tx = tid & 15;
    int ty = tid >> 4;
    int row0 = blockIdx.y * BM;
    int col0 = blockIdx.x * BN;

    float acc[4][4] = {};

    for (int k0 = 0; k0 < K; k0 += BK) {
        #pragma unroll
        for (int i = 0; i < 2; i++) {
            int lin = tid + i * 256;
            int r = lin >> 3;
            int c4 = (lin & 7) * 4;
            int row = row0 + r;
            float4 v = make_float4(0.f, 0.f, 0.f, 0.f);
            if (row < M)
                v = *(const float4*)(A + (size_t)row * K + k0 + c4);
            *(float4*)&As[r][c4] = v;
        }
        #pragma unroll
        for (int i = 0; i < 2; i++) {
            int lin = tid + i * 256;
            int kk = lin >> 4;
            int c4 = (lin & 15) * 4;
            float4 v = *(const float4*)(B + (size_t)(k0 + kk) * N + col0 + c4);
            *(float4*)&Bs[kk][c4] = v;
        }
        __syncthreads();

        #pragma unroll
        for (int k = 0; k < BK; k++) {
            float4 b4 = *(const float4*)&Bs[k][tx * 4];
            #pragma unroll
            for (int i = 0; i < 4; i++) {
                float a = As[ty * 4 + i][k];
                acc[i][0] += a * b4.x;
                acc[i][1] += a * b4.y;
                acc[i][2] += a * b4.z;
                acc[i][3] += a * b4.w;
            }
        }
        __syncthreads();
    }

    #pragma unroll
    for (int i = 0; i < 4; i++) {
        int row = row0 + ty * 4 + i;
        if (row >= M) continue;
        #pragma unroll
        for (int j = 0; j < 4; j++) {
            int col = col0 + tx * 4 + j;
            float v = acc[i][j] + bias[col];
            if (doRelu) v = fmaxf(v, 0.f);
            C[(size_t)row * N + col] = v;
        }
    }
}

// ============================================================================
// Edge kernel v2: one warp per contiguous strip of EPW edges.
// Lane l owns float4 chunk l of the 128-float rows. Each lane accumulates
// w_e * partial_dist2 across the strip in a register; warp-reduce + atomics
// only once per graph-segment per strip (~1 per warp), not per edge.
// ============================================================================
__global__ __launch_bounds__(256)
void edge_kernel(const float* __restrict__ ew,
                 const int* __restrict__ snd, const int* __restrict__ rcv,
                 int E, int G) {
    int lane = threadIdx.x & 31;
    int wl = threadIdx.x >> 5;
    int warp = blockIdx.x * 8 + wl;
    int base = warp * EPW;
    if (base >= E) return;
    int end = min(base + EPW, E);

    // graph id of first edge of the strip (one binary search per warp)
    int lo = 0, hi = G;
    while (hi - lo > 1) {
        int mid = (lo + hi) >> 1;
        if (g_eoff[mid] <= base) lo = mid; else hi = mid;
    }
    int gid = lo;
    int bnd = g_eoff[gid + 1];

    const float* __restrict__ h = g_h;
    float acc = 0.f, wacc = 0.f;
    int e = base;
    for (;;) {
        int seg = min(end, bnd);
        #pragma unroll 4
        for (; e < seg; e++) {
            int s = __ldg(snd + e);
            int r = __ldg(rcv + e);
            float w = __ldg(ew + e);
            float4 a = *(const float4*)(h + (size_t)s * DF + lane * 4);
            float4 b = *(const float4*)(h + (size_t)r * DF + lane * 4);
            float d0 = a.x - b.x, d1 = a.y - b.y;
            float d2 = a.z - b.z, d3 = a.w - b.w;
            acc += w * (d0 * d0 + d1 * d1 + d2 * d2 + d3 * d3);
            if (lane == 0) wacc += w;
        }
        // flush this graph segment
        float v = acc;
        #pragma unroll
        for (int off = 16; off; off >>= 1)
            v += __shfl_xor_sync(0xffffffffu, v, off);
        if (lane == 0) {
            atomicAdd(&g_esum[gid], v);
            atomicAdd(&g_wsum[gid], wacc);
        }
        if (e >= end) break;
        acc = 0.f; wacc = 0.f;
        gid++;
        bnd = g_eoff[gid + 1];
    }
}

// ============================================================================
// Output kernel: gather node_out rows; block 0 computes the mean loss.
// ============================================================================
__global__ void out_kernel(float* __restrict__ out, int G, int lossIdx) {
    int g = blockIdx.x;
    int t = threadIdx.x;
    if (g < G)
        out[g * DF + t] = g_h[(size_t)g_nid[g] * DF + t];
    if (g == 0) {
        __shared__ float red[128];
        float term = 0.f;
        if (t < G) {
            float w = g_wsum[t];
            term = (w != 0.f) ? (g_esum[t] / w) : 0.f;
        }
        red[t] = term;
        __syncthreads();
        #pragma unroll
        for (int s = 64; s; s >>= 1) {
            if (t < s) red[t] += red[t + s];
            __syncthreads();
        }
        if (t == 0) out[lossIdx] = red[0] / (float)G;
    }
}

// ============================================================================
extern "C" void kernel_launch(void* const* d_in, const int* in_sizes, int n_in,
                              void* d_out, int out_size) {
    const float* nodes     = (const float*)d_in[0];
    const float* edges     = (const float*)d_in[1];
    const int*   senders   = (const int*)d_in[2];
    const int*   receivers = (const int*)d_in[3];
    const int*   n_node    = (const int*)d_in[4];
    const int*   n_edge    = (const int*)d_in[5];
    const float* W1        = (const float*)d_in[6];
    const float* b1        = (const float*)d_in[7];
    const float* W2        = (const float*)d_in[8];
    const float* b2        = (const float*)d_in[9];
    float* out = (float*)d_out;

    int M = in_sizes[0] / DF;
    int E = in_sizes[2];
    int G = in_sizes[4];

    void *p_tmp = nullptr, *p_h = nullptr;
    cudaGetSymbolAddress(&p_tmp, g_tmp);
    cudaGetSymbolAddress(&p_h, g_h);

    prefix_kernel<<<1, 128>>>(n_node, n_edge, G);

    dim3 g1(DH / 64, (M + 63) / 64);
    gemm_bias_act<<<g1, 256>>>(nodes, W1, b1, (float*)p_tmp, M, DH, DF, 1);

    dim3 g2(DF / 64, (M + 63) / 64);
    gemm_bias_act<<<g2, 256>>>((float*)p_tmp, W2, b2, (float*)p_h, M, DF, DH, 0);

    int eblocks = (E + EPW * 8 - 1) / (EPW * 8);
    edge_kernel<<<eblocks, 256>>>(edges, senders, receivers, E, G);

    out_kernel<<<G, 128>>>(out, G, out_size - 1);
}